// round 13
// baseline (speedup 1.0000x reference)
#include <cuda_runtime.h>
#include <cuda_bf16.h>

// B=64, H=W=1024, patch=64 -> 16x16 = 256 patches/img.
// final = mean_b( max_patch( mean_{64x64} |o - t| ) )
//
// Empirical optimum (78.2-78.6us across three independent benches): one block
// per PAIR of horizontally adjacent patches, grid = 64*16*8 = 8192, 256
// threads. Thread tid owns float4-col (tid&31) and row group (tid>>5); 8
// o-loads then 8 t-loads, all 16 LDG.128 front-batched (MLP=16). Lanes 0-15
// hold patch0, 16-31 patch1: half-warp shuffle yields both patch sums per
// warp. Fused last-block epilogue (per-image atomicMax on monotone fp32 bits
// + wrap-safe counter), graph-replay safe. Achieves ~6.87 TB/s = the chip's
// effective streaming-read ceiling for this access pattern; traffic (512 MB,
// zero reuse) is irreducible, so this is the roofline.

#define B 64
#define HW 1024
#define P 64
#define NBLOCKS (B * 16 * 8)            // 8192
#define PATCH_ELEMS (P * P)             // 4096

__device__ unsigned int g_img_max[B];   // zero-init; re-zeroed by last block
__device__ unsigned int g_counter;      // monotone, wrap-safe

__global__ __launch_bounds__(256, 3) void patch_loss_pair_kernel(
    const float* __restrict__ o, const float* __restrict__ t,
    float* __restrict__ out)
{
    const int blk  = blockIdx.x;          // 0..8191
    const int img  = blk >> 7;            // /128
    const int ph   = (blk >> 3) & 15;
    const int pair = blk & 7;             // patch-col pair 0..7

    // pair covers cols [pair*128, pair*128+128)
    const size_t base = (size_t)img * (HW * HW) + (size_t)ph * (P * HW)
                      + (size_t)pair * 128;
    const float4* __restrict__ o4 = reinterpret_cast<const float4*>(o + base);
    const float4* __restrict__ t4 = reinterpret_cast<const float4*>(t + base);

    const int tid = threadIdx.x;
    const int col = tid & 31;             // float4 col within pair (== lane)
    const int rg  = tid >> 5;             // row group 0..7

    // rows handled: rg + i*8, i = 0..7; row stride = 256 float4
    const int off0 = rg * 256 + col;

    float4 av[8], bv[8];
#pragma unroll
    for (int i = 0; i < 8; i++) av[i] = __ldcs(&o4[off0 + i * 2048]);
#pragma unroll
    for (int i = 0; i < 8; i++) bv[i] = __ldcs(&t4[off0 + i * 2048]);

    float acc = 0.0f;
#pragma unroll
    for (int i = 0; i < 8; i++) {
        acc += fabsf(av[i].x - bv[i].x) + fabsf(av[i].y - bv[i].y)
             + fabsf(av[i].z - bv[i].z) + fabsf(av[i].w - bv[i].w);
    }

    // Reduce within each 16-lane half (one patch per half).
#pragma unroll
    for (int s = 8; s > 0; s >>= 1)
        acc += __shfl_xor_sync(0xFFFFFFFFu, acc, s);

    __shared__ float warp_sums[2][8];
    __shared__ bool s_is_last;
    const int lane = tid & 31;
    const int wid = tid >> 5;
    if (lane == 0)  warp_sums[0][wid] = acc;   // patch0 partial (rows of rg)
    if (lane == 16) warp_sums[1][wid] = acc;   // patch1 partial
    __syncthreads();

    if (tid == 0) {
        float v0 = 0.f, v1 = 0.f;
#pragma unroll
        for (int w = 0; w < 8; w++) { v0 += warp_sums[0][w]; v1 += warp_sums[1][w]; }
        // sums >= 0: float bits monotone as unsigned
        atomicMax(&g_img_max[img], __float_as_uint(v0));
        atomicMax(&g_img_max[img], __float_as_uint(v1));
        __threadfence();
        unsigned int old = atomicAdd(&g_counter, 1u);
        s_is_last = ((old % NBLOCKS) == (NBLOCKS - 1));
    }
    __syncthreads();

    if (s_is_last) {
        __threadfence();
        __shared__ float red[2];
        if (wid < 2) {
            int i = wid * 32 + lane;                     // 0..63
            unsigned int bits = atomicOr(&g_img_max[i], 0u);
            float m = __uint_as_float(bits);
#pragma unroll
            for (int s = 16; s > 0; s >>= 1)
                m += __shfl_xor_sync(0xFFFFFFFFu, m, s);
            if (lane == 0) red[wid] = m;
        }
        __syncthreads();
        if (tid == 0)
            *out = (red[0] + red[1]) * (1.0f / (float)PATCH_ELEMS / (float)B);
        __syncthreads();
        if (tid < B) g_img_max[tid] = 0u;   // reset for next replay
    }
}

extern "C" void kernel_launch(void* const* d_in, const int* in_sizes, int n_in,
                              void* d_out, int out_size)
{
    const float* o = (const float*)d_in[0];
    const float* t = (const float*)d_in[1];
    float* out = (float*)d_out;
    patch_loss_pair_kernel<<<NBLOCKS, 256>>>(o, t, out);
}

// round 16
// speedup vs baseline: 1.0082x; 1.0082x over previous
#include <cuda_runtime.h>
#include <cuda_bf16.h>

// B=64, H=W=1024, patch=64 -> 16x16 = 256 patches/img.
// final = mean_b( max_patch( mean_{64x64} |o - t| ) )
//
// Empirical optimum, validated 4x (78.21 / 78.59 / 78.34 / 78.59 us):
// one block per PAIR of horizontally adjacent patches, grid = 64*16*8 = 8192,
// 256 threads. Thread tid owns float4-col (tid&31) and row group (tid>>5);
// 8 o-loads then 8 t-loads, all 16 LDG.128 front-batched (MLP=16, regs 72,
// 3 CTAs/SM). Lanes 0-15 hold patch0, 16-31 patch1: half-warp shuffle yields
// both patch sums per warp. Fused last-block epilogue (per-image atomicMax on
// monotone fp32 bits + wrap-safe monotone counter), graph-replay safe.
// Sustains ~6.85 TB/s = the chip's achieved streaming-read ceiling; the
// 512 MB of traffic is irreducible (zero reuse, exact fp32), so this is the
// roofline for this problem.

#define B 64
#define HW 1024
#define P 64
#define NBLOCKS (B * 16 * 8)            // 8192
#define PATCH_ELEMS (P * P)             // 4096

__device__ unsigned int g_img_max[B];   // zero-init; re-zeroed by last block
__device__ unsigned int g_counter;      // monotone, wrap-safe

__global__ __launch_bounds__(256, 3) void patch_loss_pair_kernel(
    const float* __restrict__ o, const float* __restrict__ t,
    float* __restrict__ out)
{
    const int blk  = blockIdx.x;          // 0..8191
    const int img  = blk >> 7;            // /128
    const int ph   = (blk >> 3) & 15;
    const int pair = blk & 7;             // patch-col pair 0..7

    // pair covers cols [pair*128, pair*128+128)
    const size_t base = (size_t)img * (HW * HW) + (size_t)ph * (P * HW)
                      + (size_t)pair * 128;
    const float4* __restrict__ o4 = reinterpret_cast<const float4*>(o + base);
    const float4* __restrict__ t4 = reinterpret_cast<const float4*>(t + base);

    const int tid = threadIdx.x;
    const int col = tid & 31;             // float4 col within pair (== lane)
    const int rg  = tid >> 5;             // row group 0..7

    // rows handled: rg + i*8, i = 0..7; row stride = 256 float4
    const int off0 = rg * 256 + col;

    float4 av[8], bv[8];
#pragma unroll
    for (int i = 0; i < 8; i++) av[i] = __ldcs(&o4[off0 + i * 2048]);
#pragma unroll
    for (int i = 0; i < 8; i++) bv[i] = __ldcs(&t4[off0 + i * 2048]);

    float acc = 0.0f;
#pragma unroll
    for (int i = 0; i < 8; i++) {
        acc += fabsf(av[i].x - bv[i].x) + fabsf(av[i].y - bv[i].y)
             + fabsf(av[i].z - bv[i].z) + fabsf(av[i].w - bv[i].w);
    }

    // Reduce within each 16-lane half (one patch per half).
#pragma unroll
    for (int s = 8; s > 0; s >>= 1)
        acc += __shfl_xor_sync(0xFFFFFFFFu, acc, s);

    __shared__ float warp_sums[2][8];
    __shared__ bool s_is_last;
    const int lane = tid & 31;
    const int wid = tid >> 5;
    if (lane == 0)  warp_sums[0][wid] = acc;   // patch0 partial (rows of rg)
    if (lane == 16) warp_sums[1][wid] = acc;   // patch1 partial
    __syncthreads();

    if (tid == 0) {
        float v0 = 0.f, v1 = 0.f;
#pragma unroll
        for (int w = 0; w < 8; w++) { v0 += warp_sums[0][w]; v1 += warp_sums[1][w]; }
        // sums >= 0: float bits monotone as unsigned
        atomicMax(&g_img_max[img], __float_as_uint(v0));
        atomicMax(&g_img_max[img], __float_as_uint(v1));
        __threadfence();
        unsigned int old = atomicAdd(&g_counter, 1u);
        s_is_last = ((old % NBLOCKS) == (NBLOCKS - 1));
    }
    __syncthreads();

    if (s_is_last) {
        __threadfence();
        __shared__ float red[2];
        if (wid < 2) {
            int i = wid * 32 + lane;                     // 0..63
            unsigned int bits = atomicOr(&g_img_max[i], 0u);
            float m = __uint_as_float(bits);
#pragma unroll
            for (int s = 16; s > 0; s >>= 1)
                m += __shfl_xor_sync(0xFFFFFFFFu, m, s);
            if (lane == 0) red[wid] = m;
        }
        __syncthreads();
        if (tid == 0)
            *out = (red[0] + red[1]) * (1.0f / (float)PATCH_ELEMS / (float)B);
        __syncthreads();
        if (tid < B) g_img_max[tid] = 0u;   // reset for next replay
    }
}

extern "C" void kernel_launch(void* const* d_in, const int* in_sizes, int n_in,
                              void* d_out, int out_size)
{
    const float* o = (const float*)d_in[0];
    const float* t = (const float*)d_in[1];
    float* out = (float*)d_out;
    patch_loss_pair_kernel<<<NBLOCKS, 256>>>(o, t, out);
}